// round 4
// baseline (speedup 1.0000x reference)
#include <cuda_runtime.h>
#include <math.h>

// Problem constants (match reference)
#define Hc 384
#define Wc 384
#define Bc 4
#define Mc 192
#define EPSc 1e-6f
#define MAXD 543.0580079f        // sqrt(384^2 + 384^2)
#define Cc (EPSc / MAXD)         // EPS / MAX_DIST

// Tiling
#define TPB 128
#define JT 3          // columns per thread: 128*3 = 384 = W
#define RR 2          // rows per block
#define MC 8          // m-chunk (4 packed pairs)
#define TILES (Hc / RR)            // 192 row tiles per image
#define NBLOCKS (Bc * TILES)       // 768 blocks

// Persistent scratch. Zero-init is semantically "+inf" for t2 keys
// (key = 0x7F800000 - bits, atomicMax), and 0 for the arrival counter.
// The finisher block resets both -> deterministic graph replays.
__device__ int   g_t2key[Bc * Mc];
__device__ float g_t1part[NBLOCKS];
__device__ float g_ppart[NBLOCKS];
__device__ int   g_ctr;

// ---- Blackwell packed fp32x2 helpers ----
__device__ __forceinline__ float2 f2add(float2 a, float2 b) {
    unsigned long long ua = *reinterpret_cast<unsigned long long*>(&a);
    unsigned long long ub = *reinterpret_cast<unsigned long long*>(&b);
    unsigned long long ur;
    asm("add.rn.f32x2 %0, %1, %2;" : "=l"(ur) : "l"(ua), "l"(ub));
    return *reinterpret_cast<float2*>(&ur);
}
__device__ __forceinline__ float2 f2sub(float2 a, float2 b) {
    unsigned long long ua = *reinterpret_cast<unsigned long long*>(&a);
    unsigned long long ub = *reinterpret_cast<unsigned long long*>(&b);
    unsigned long long ur;
    asm("sub.rn.f32x2 %0, %1, %2;" : "=l"(ur) : "l"(ua), "l"(ub));
    return *reinterpret_cast<float2*>(&ur);
}
__device__ __forceinline__ float2 f2mul(float2 a, float2 b) {
    unsigned long long ua = *reinterpret_cast<unsigned long long*>(&a);
    unsigned long long ub = *reinterpret_cast<unsigned long long*>(&b);
    unsigned long long ur;
    asm("mul.rn.f32x2 %0, %1, %2;" : "=l"(ur) : "l"(ua), "l"(ub));
    return *reinterpret_cast<float2*>(&ur);
}
// warp-min of a nonneg float via integer redux (bit pattern is monotonic)
__device__ __forceinline__ unsigned redux_min_u32(unsigned v) {
    unsigned r;
    asm("redux.sync.min.u32 %0, %1, 0xffffffff;" : "=r"(r) : "r"(v));
    return r;
}

__global__ __launch_bounds__(TPB) void whd_kernel(
    const float* __restrict__ prob,
    const float* __restrict__ gt,
    const float* __restrict__ osz,
    float* __restrict__ out)
{
    const int blk  = blockIdx.x;
    const int b    = blk / TILES;
    const int row0 = (blk % TILES) * RR;
    const int tid  = threadIdx.x;
    const int lane = tid & 31;
    const int wrp  = tid >> 5;

    __shared__ __align__(16) float s_gx[Mc];
    __shared__ __align__(16) float s_dy2[RR * Mc];
    __shared__ float s_red[8];
    __shared__ int s_last;

    const float fy = osz[b * 2 + 0] * (1.0f / (float)Hc);
    const float fx = osz[b * 2 + 1] * (1.0f / (float)Wc);

    // gt prologue: 128 threads cover 192 points (1.5 each)
    {
        const float2* gt2 = (const float2*)gt;
        for (int m = tid; m < Mc; m += TPB) {
            float2 g = gt2[b * Mc + m];
            float gy = g.x * fy;
            s_gx[m] = g.y * fx;
#pragma unroll
            for (int k = 0; k < RR; k++) {
                float dy = (float)(row0 + k) * fy - gy;
                s_dy2[k * Mc + m] = dy * dy;
            }
        }
    }

    // Per-pixel p and 1/w^2 (w = p^4 + EPS/MAX_DIST), duplicated for f32x2
    const float* pimg = prob + b * Hc * Wc;
    float  pr[RR][JT];
    float2 iw2d[RR][JT];
    float2 xjd[JT];
#pragma unroll
    for (int jt = 0; jt < JT; jt++) {
        float xv = (float)(tid + jt * TPB) * fx;
        xjd[jt] = make_float2(xv, xv);
    }
#pragma unroll
    for (int i = 0; i < RR; i++) {
#pragma unroll
        for (int jt = 0; jt < JT; jt++) {
            float p = pimg[(row0 + i) * Wc + tid + jt * TPB];
            pr[i][jt] = p;
            float p2 = p * p;
            float w  = p2 * p2 + Cc;
            float iw = __fdividef(1.0f, w);
            float iw2 = iw * iw;
            iw2d[i][jt] = make_float2(iw2, iw2);
        }
    }
    __syncthreads();

    float pixmin[RR][JT];
#pragma unroll
    for (int i = 0; i < RR; i++)
#pragma unroll
        for (int jt = 0; jt < JT; jt++) pixmin[i][jt] = 3.0e38f;

    const float2* s_gx2 = (const float2*)s_gx;

    for (int m0 = 0; m0 < Mc; m0 += MC) {
        float2 dx2p[JT][MC / 2];
        float2 t2p[MC / 2];
#pragma unroll
        for (int mp = 0; mp < MC / 2; mp++) {
            float2 gxp = s_gx2[(m0 >> 1) + mp];          // broadcast LDS.64
            t2p[mp] = make_float2(3.0e38f, 3.0e38f);
#pragma unroll
            for (int jt = 0; jt < JT; jt++) {
                float2 dxp = f2sub(xjd[jt], gxp);
                dx2p[jt][mp] = f2mul(dxp, dxp);
            }
        }
#pragma unroll
        for (int i = 0; i < RR; i++) {
            const float2* dy2row = (const float2*)(s_dy2 + i * Mc + m0);
#pragma unroll
            for (int mp = 0; mp < MC / 2; mp++) {
                float2 dy2p = dy2row[mp];                 // broadcast LDS.64
#pragma unroll
                for (int jt = 0; jt < JT; jt++) {
                    float2 d2 = f2add(dy2p, dx2p[jt][mp]);
                    float2 t  = f2mul(d2, iw2d[i][jt]);
                    pixmin[i][jt] = fminf(pixmin[i][jt], fminf(d2.x, d2.y));
                    t2p[mp].x = fminf(t2p[mp].x, t.x);
                    t2p[mp].y = fminf(t2p[mp].y, t.y);
                }
            }
        }
        // warp-min via redux.sync, one RED per (warp, m)
#pragma unroll
        for (int mc = 0; mc < MC; mc++) {
            float v = (mc & 1) ? t2p[mc >> 1].y : t2p[mc >> 1].x;
            unsigned u = redux_min_u32(__float_as_uint(v));
            if (lane == mc)
                atomicMax(&g_t2key[b * Mc + m0 + mc], 0x7F800000 - (int)u);
        }
    }

    // term1 partials: sum p * sqrt(min_m d2), and sum p
    float t1p = 0.0f, pp = 0.0f;
#pragma unroll
    for (int i = 0; i < RR; i++) {
#pragma unroll
        for (int jt = 0; jt < JT; jt++) {
            t1p += pr[i][jt] * sqrtf(pixmin[i][jt]);
            pp  += pr[i][jt];
        }
    }
#pragma unroll
    for (int off = 16; off >= 1; off >>= 1) {
        t1p += __shfl_xor_sync(0xffffffffu, t1p, off);
        pp  += __shfl_xor_sync(0xffffffffu, pp,  off);
    }
    if (lane == 0) { s_red[wrp] = t1p; s_red[4 + wrp] = pp; }
    __syncthreads();
    if (tid == 0) {
        g_t1part[blk] = s_red[0] + s_red[1] + s_red[2] + s_red[3];
        g_ppart[blk]  = s_red[4] + s_red[5] + s_red[6] + s_red[7];
    }

    // ---- last-block finalize ----
    __threadfence();
    __syncthreads();
    if (tid == 0) s_last = (atomicAdd(&g_ctr, 1) == NBLOCKS - 1);
    __syncthreads();
    if (!s_last) return;

    // term2: thread tid owns 6 consecutive keys, all within image (tid>>5)
    // (768 keys / 128 threads; 192 per image / 32 lanes = 6 per lane)
    __shared__ float s_t2[Bc], s_t1s[Bc], s_pps[Bc];
    {
        float acc = 0.0f;
#pragma unroll
        for (int k = 0; k < 6; k++) {
            int idx = tid * 6 + k;
            int key = __ldcg(&g_t2key[idx]);
            float v = __int_as_float(0x7F800000 - key);
            acc += fminf(sqrtf(v), MAXD);
            g_t2key[idx] = 0;                    // reset for next call
        }
#pragma unroll
        for (int off = 16; off >= 1; off >>= 1)
            acc += __shfl_xor_sync(0xffffffffu, acc, off);
        if (lane == 0) s_t2[wrp] = acc;          // warp w == image w
    }

    // term1: warp w reduces the 192 block-partials of image w (6 per lane)
    {
        float t1 = 0.0f, ps = 0.0f;
#pragma unroll
        for (int k = 0; k < 6; k++) {
            int idx = wrp * TILES + k * 32 + lane;
            t1 += __ldcg(&g_t1part[idx]);
            ps += __ldcg(&g_ppart[idx]);
        }
#pragma unroll
        for (int off = 16; off >= 1; off >>= 1) {
            t1 += __shfl_xor_sync(0xffffffffu, t1, off);
            ps += __shfl_xor_sync(0xffffffffu, ps, off);
        }
        if (lane == 0) { s_t1s[wrp] = t1; s_pps[wrp] = ps; }
    }
    __syncthreads();
    if (tid == 0) {
        float res = 0.0f;
#pragma unroll
        for (int b2 = 0; b2 < Bc; b2++) {
            res += s_t1s[b2] / (s_pps[b2] + EPSc);
            res += s_t2[b2] * (1.0f / (float)Mc);
        }
        out[0] = res * (1.0f / (float)Bc);
        g_ctr = 0;                               // reset for next call
    }
}

extern "C" void kernel_launch(void* const* d_in, const int* in_sizes, int n_in,
                              void* d_out, int out_size) {
    const float* prob = (const float*)d_in[0];
    const float* gt   = (const float*)d_in[1];
    const float* osz  = (const float*)d_in[2];
    float* out = (float*)d_out;

    whd_kernel<<<NBLOCKS, TPB>>>(prob, gt, osz, out);
}

// round 5
// speedup vs baseline: 3.1878x; 3.1878x over previous
#include <cuda_runtime.h>
#include <math.h>

// Problem constants (match reference)
#define Hc 384
#define Wc 384
#define Bc 4
#define Mc 192
#define EPSc 1e-6f
#define MAXD 543.0580079f        // sqrt(384^2 + 384^2)
#define Cc (EPSc / MAXD)         // EPS / MAX_DIST

// Tiling (R2-proven shape)
#define TPB 128
#define JT 3          // columns per thread: 128*3 = 384 = W
#define RR 6          // rows per block
#define MC 8          // m-chunk
#define TILES (Hc / RR)            // 64 row tiles per image
#define NBLOCKS (Bc * TILES)       // 256 blocks

// Persistent scratch. Zero-init is semantically "+inf" for t2 keys
// (key = 0x7F800000 - bits, atomicMax), 0 for the counter.
// Finisher block resets both -> deterministic graph replays.
__device__ int   g_t2key[Bc * Mc];
__device__ float g_t1part[NBLOCKS];
__device__ float g_ppart[NBLOCKS];
__device__ int   g_ctr;

__global__ __launch_bounds__(TPB) void whd_kernel(
    const float* __restrict__ prob,
    const float* __restrict__ gt,
    const float* __restrict__ osz,
    float* __restrict__ out)
{
    const int blk  = blockIdx.x;
    const int b    = blk / TILES;
    const int row0 = (blk % TILES) * RR;
    const int tid  = threadIdx.x;
    const int lane = tid & 31;
    const int wrp  = tid >> 5;

    __shared__ float s_gx[Mc];
    __shared__ float s_dy2[RR * Mc];
    __shared__ __align__(16) int s_t2min[Mc * 32];   // [m][lane], float bits
    __shared__ float s_red[8];
    __shared__ int s_last;

    // init block-local t2 table to +inf (vectorized: 12 ST.128 per thread)
    {
        int4 inf4 = make_int4(0x7F800000, 0x7F800000, 0x7F800000, 0x7F800000);
        int4* p4 = (int4*)s_t2min;
#pragma unroll
        for (int k = 0; k < (Mc * 32 / 4) / TPB; k++)
            p4[tid + k * TPB] = inf4;
    }

    const float fy = osz[b * 2 + 0] * (1.0f / (float)Hc);
    const float fx = osz[b * 2 + 1] * (1.0f / (float)Wc);

    // gt prologue: normalized coords, per-row dy^2
    {
        const float2* gt2 = (const float2*)gt;
        for (int m = tid; m < Mc; m += TPB) {
            float2 g = gt2[b * Mc + m];
            float gy = g.x * fy;
            s_gx[m] = g.y * fx;
#pragma unroll
            for (int k = 0; k < RR; k++) {
                float dy = (float)(row0 + k) * fy - gy;
                s_dy2[k * Mc + m] = dy * dy;
            }
        }
    }

    // Per-pixel p and 1/w^2  (w = p^4 + EPS/MAX_DIST)
    const float* pimg = prob + b * Hc * Wc;
    float pr[RR][JT];
    float iw2[RR][JT];
    float xj[JT];
#pragma unroll
    for (int jt = 0; jt < JT; jt++) xj[jt] = (float)(tid + jt * TPB) * fx;
#pragma unroll
    for (int i = 0; i < RR; i++) {
#pragma unroll
        for (int jt = 0; jt < JT; jt++) {
            float p = pimg[(row0 + i) * Wc + tid + jt * TPB];
            pr[i][jt] = p;
            float p2 = p * p;
            float w  = p2 * p2 + Cc;
            float iw = __fdividef(1.0f, w);
            iw2[i][jt] = iw * iw;
        }
    }
    __syncthreads();

    float pixmin[RR][JT];
#pragma unroll
    for (int i = 0; i < RR; i++)
#pragma unroll
        for (int jt = 0; jt < JT; jt++) pixmin[i][jt] = 3.0e38f;

    for (int m0 = 0; m0 < Mc; m0 += MC) {
        float t2acc[MC];
        float dx2r[JT][MC];
#pragma unroll
        for (int mc = 0; mc < MC; mc++) {
            t2acc[mc] = 3.0e38f;
            float gx = s_gx[m0 + mc];                    // broadcast LDS
#pragma unroll
            for (int jt = 0; jt < JT; jt++) {
                float dx = xj[jt] - gx;
                dx2r[jt][mc] = dx * dx;
            }
        }
#pragma unroll
        for (int i = 0; i < RR; i++) {
#pragma unroll
            for (int mc = 0; mc < MC; mc++) {
                float dy2 = s_dy2[i * Mc + m0 + mc];     // broadcast LDS
#pragma unroll
                for (int jt = 0; jt < JT; jt++) {
                    float d2 = dy2 + dx2r[jt][mc];
                    pixmin[i][jt] = fminf(pixmin[i][jt], d2);
                    float t = d2 * iw2[i][jt];
                    t2acc[mc] = fminf(t2acc[mc], t);
                }
            }
        }
        // per-lane mins -> block t2 table (spread-bank ATOMS, no result dep)
#pragma unroll
        for (int mc = 0; mc < MC; mc++)
            atomicMin(&s_t2min[(m0 + mc) * 32 + lane], __float_as_int(t2acc[mc]));
    }

    // term1 partials: sum p * sqrt(min_m d2), and sum p
    float t1p = 0.0f, pp = 0.0f;
#pragma unroll
    for (int i = 0; i < RR; i++) {
#pragma unroll
        for (int jt = 0; jt < JT; jt++) {
            t1p += pr[i][jt] * sqrtf(pixmin[i][jt]);
            pp  += pr[i][jt];
        }
    }
#pragma unroll
    for (int off = 16; off >= 1; off >>= 1) {
        t1p += __shfl_xor_sync(0xffffffffu, t1p, off);
        pp  += __shfl_xor_sync(0xffffffffu, pp,  off);
    }
    if (lane == 0) { s_red[wrp] = t1p; s_red[4 + wrp] = pp; }
    __syncthreads();   // also covers s_t2min writes
    if (tid == 0) {
        g_t1part[blk] = s_red[0] + s_red[1] + s_red[2] + s_red[3];
        g_ppart[blk]  = s_red[4] + s_red[5] + s_red[6] + s_red[7];
    }

    // block t2 table -> global keys (192 m over 128 threads: m=tid, m=128+tid<192)
    {
        for (int m = tid; m < Mc; m += TPB) {
            const int4* row = (const int4*)&s_t2min[m * 32];
            int4 a = row[0], c = row[1], d = row[2], e = row[3];
            int v0 = min(min(a.x, a.y), min(a.z, a.w));
            int v1 = min(min(c.x, c.y), min(c.z, c.w));
            int v2 = min(min(d.x, d.y), min(d.z, d.w));
            int v3 = min(min(e.x, e.y), min(e.z, e.w));
            int4 f = row[4], g = row[5], h2 = row[6], k2 = row[7];
            int v4 = min(min(f.x, f.y), min(f.z, f.w));
            int v5 = min(min(g.x, g.y), min(g.z, g.w));
            int v6 = min(min(h2.x, h2.y), min(h2.z, h2.w));
            int v7 = min(min(k2.x, k2.y), min(k2.z, k2.w));
            int v = min(min(min(v0, v1), min(v2, v3)),
                        min(min(v4, v5), min(v6, v7)));
            atomicMax(&g_t2key[b * Mc + m], 0x7F800000 - v);
        }
    }

    // ---- last-block finalize ----
    __threadfence();
    __syncthreads();
    if (tid == 0) s_last = (atomicAdd(&g_ctr, 1) == NBLOCKS - 1);
    __syncthreads();
    if (!s_last) return;

    __shared__ float s_t2[Bc], s_t1s[Bc], s_pps[Bc];
    // term2: 768 keys over 128 threads, 6 each, all in image (tid>>5 ... )
    // use layout: thread handles keys tid*6 .. tid*6+5 (contiguous, same image
    // iff tid*6/192 constant across the 6 -> true since 192 % 6 == 0)
    {
        float acc = 0.0f;
#pragma unroll
        for (int k = 0; k < 6; k++) {
            int idx = tid * 6 + k;
            int key = __ldcg(&g_t2key[idx]);
            float v = __int_as_float(0x7F800000 - key);
            acc += fminf(sqrtf(v), MAXD);
            g_t2key[idx] = 0;                    // reset for next call
        }
        // all 6 keys of this thread belong to image (tid*6)/192 = tid/32 = wrp
#pragma unroll
        for (int off = 16; off >= 1; off >>= 1)
            acc += __shfl_xor_sync(0xffffffffu, acc, off);
        if (lane == 0) s_t2[wrp] = acc;          // warp w == image w
    }
    // term1: warp w reduces the 64 block-partials of image w (2 per lane)
    {
        float t1 = 0.0f, ps = 0.0f;
        if (wrp < Bc) {
            t1 = __ldcg(&g_t1part[wrp * TILES + lane]) +
                 __ldcg(&g_t1part[wrp * TILES + 32 + lane]);
            ps = __ldcg(&g_ppart [wrp * TILES + lane]) +
                 __ldcg(&g_ppart [wrp * TILES + 32 + lane]);
#pragma unroll
            for (int off = 16; off >= 1; off >>= 1) {
                t1 += __shfl_xor_sync(0xffffffffu, t1, off);
                ps += __shfl_xor_sync(0xffffffffu, ps, off);
            }
            if (lane == 0) { s_t1s[wrp] = t1; s_pps[wrp] = ps; }
        }
    }
    __syncthreads();
    if (tid == 0) {
        float res = 0.0f;
#pragma unroll
        for (int b2 = 0; b2 < Bc; b2++) {
            res += s_t1s[b2] / (s_pps[b2] + EPSc);
            res += s_t2[b2] * (1.0f / (float)Mc);
        }
        out[0] = res * (1.0f / (float)Bc);
        g_ctr = 0;                               // reset for next call
    }
}

extern "C" void kernel_launch(void* const* d_in, const int* in_sizes, int n_in,
                              void* d_out, int out_size) {
    const float* prob = (const float*)d_in[0];
    const float* gt   = (const float*)d_in[1];
    const float* osz  = (const float*)d_in[2];
    float* out = (float*)d_out;

    whd_kernel<<<NBLOCKS, TPB>>>(prob, gt, osz, out);
}

// round 6
// speedup vs baseline: 3.6453x; 1.1435x over previous
#include <cuda_runtime.h>
#include <math.h>

// Problem constants (match reference)
#define Hc 384
#define Wc 384
#define Bc 4
#define Mc 192
#define EPSc 1e-6f
#define MAXD 543.0580079f        // sqrt(384^2 + 384^2)
#define Cc (EPSc / MAXD)         // EPS / MAX_DIST

// Tiling (R5-proven shape)
#define TPB 128
#define JT 3          // columns per thread: 128*3 = 384 = W
#define RR 6          // rows per block
#define MC 8          // m-chunk (4 packed pairs)
#define TILES (Hc / RR)            // 64 row tiles per image
#define NBLOCKS (Bc * TILES)       // 256 blocks

// Persistent scratch. Zero-init is semantically "+inf" for t2 keys
// (key = 0x7F800000 - bits, atomicMax), 0 for the counter.
// Finisher block resets both -> deterministic graph replays.
__device__ int   g_t2key[Bc * Mc];
__device__ float g_t1part[NBLOCKS];
__device__ float g_ppart[NBLOCKS];
__device__ int   g_ctr;

// ---- Blackwell packed fp32x2 helpers ----
__device__ __forceinline__ float2 f2add(float2 a, float2 b) {
    unsigned long long ua = *reinterpret_cast<unsigned long long*>(&a);
    unsigned long long ub = *reinterpret_cast<unsigned long long*>(&b);
    unsigned long long ur;
    asm("add.rn.f32x2 %0, %1, %2;" : "=l"(ur) : "l"(ua), "l"(ub));
    return *reinterpret_cast<float2*>(&ur);
}
__device__ __forceinline__ float2 f2sub(float2 a, float2 b) {
    unsigned long long ua = *reinterpret_cast<unsigned long long*>(&a);
    unsigned long long ub = *reinterpret_cast<unsigned long long*>(&b);
    unsigned long long ur;
    asm("sub.rn.f32x2 %0, %1, %2;" : "=l"(ur) : "l"(ua), "l"(ub));
    return *reinterpret_cast<float2*>(&ur);
}
__device__ __forceinline__ float2 f2mul(float2 a, float2 b) {
    unsigned long long ua = *reinterpret_cast<unsigned long long*>(&a);
    unsigned long long ub = *reinterpret_cast<unsigned long long*>(&b);
    unsigned long long ur;
    asm("mul.rn.f32x2 %0, %1, %2;" : "=l"(ur) : "l"(ua), "l"(ub));
    return *reinterpret_cast<float2*>(&ur);
}

__global__ __launch_bounds__(TPB) void whd_kernel(
    const float* __restrict__ prob,
    const float* __restrict__ gt,
    const float* __restrict__ osz,
    float* __restrict__ out)
{
    const int blk  = blockIdx.x;
    const int b    = blk / TILES;
    const int row0 = (blk % TILES) * RR;
    const int tid  = threadIdx.x;
    const int lane = tid & 31;
    const int wrp  = tid >> 5;

    __shared__ __align__(16) float s_gx[Mc];
    __shared__ __align__(16) float s_dy2[RR * Mc];
    __shared__ __align__(16) int s_t2min[Mc * 32];   // [m][lane], float bits
    __shared__ float s_red[8];
    __shared__ int s_last;

    // init block-local t2 table to +inf (12 ST.128 per thread)
    {
        int4 inf4 = make_int4(0x7F800000, 0x7F800000, 0x7F800000, 0x7F800000);
        int4* p4 = (int4*)s_t2min;
#pragma unroll
        for (int k = 0; k < (Mc * 32 / 4) / TPB; k++)
            p4[tid + k * TPB] = inf4;
    }

    const float fy = osz[b * 2 + 0] * (1.0f / (float)Hc);
    const float fx = osz[b * 2 + 1] * (1.0f / (float)Wc);

    // gt prologue: normalized coords, per-row dy^2
    {
        const float2* gt2 = (const float2*)gt;
        for (int m = tid; m < Mc; m += TPB) {
            float2 g = gt2[b * Mc + m];
            float gy = g.x * fy;
            s_gx[m] = g.y * fx;
#pragma unroll
            for (int k = 0; k < RR; k++) {
                float dy = (float)(row0 + k) * fy - gy;
                s_dy2[k * Mc + m] = dy * dy;
            }
        }
    }

    // Per-pixel p and 1/w^2 (w = p^4 + EPS/MAX_DIST), duplicated for f32x2
    const float* pimg = prob + b * Hc * Wc;
    float  pr[RR][JT];
    float2 iw2d[RR][JT];
    float2 xjd[JT];
#pragma unroll
    for (int jt = 0; jt < JT; jt++) {
        float xv = (float)(tid + jt * TPB) * fx;
        xjd[jt] = make_float2(xv, xv);
    }
#pragma unroll
    for (int i = 0; i < RR; i++) {
#pragma unroll
        for (int jt = 0; jt < JT; jt++) {
            float p = pimg[(row0 + i) * Wc + tid + jt * TPB];
            pr[i][jt] = p;
            float p2 = p * p;
            float w  = p2 * p2 + Cc;
            float iw = __fdividef(1.0f, w);
            float iw2 = iw * iw;
            iw2d[i][jt] = make_float2(iw2, iw2);
        }
    }
    __syncthreads();

    float pixmin[RR][JT];
#pragma unroll
    for (int i = 0; i < RR; i++)
#pragma unroll
        for (int jt = 0; jt < JT; jt++) pixmin[i][jt] = 3.0e38f;

    const float2* s_gx2 = (const float2*)s_gx;

    for (int m0 = 0; m0 < Mc; m0 += MC) {
        float2 dx2p[JT][MC / 2];
        float2 t2p[MC / 2];
#pragma unroll
        for (int mp = 0; mp < MC / 2; mp++) {
            float2 gxp = s_gx2[(m0 >> 1) + mp];          // broadcast LDS.64
            t2p[mp] = make_float2(3.0e38f, 3.0e38f);
#pragma unroll
            for (int jt = 0; jt < JT; jt++) {
                float2 dxp = f2sub(xjd[jt], gxp);
                dx2p[jt][mp] = f2mul(dxp, dxp);
            }
        }
#pragma unroll
        for (int i = 0; i < RR; i++) {
            const float2* dy2row = (const float2*)(s_dy2 + i * Mc + m0);
#pragma unroll
            for (int mp = 0; mp < MC / 2; mp++) {
                float2 dy2p = dy2row[mp];                 // broadcast LDS.64
#pragma unroll
                for (int jt = 0; jt < JT; jt++) {
                    float2 d2 = f2add(dy2p, dx2p[jt][mp]);
                    float2 t  = f2mul(d2, iw2d[i][jt]);
                    pixmin[i][jt] = fminf(pixmin[i][jt], fminf(d2.x, d2.y));
                    t2p[mp].x = fminf(t2p[mp].x, t.x);
                    t2p[mp].y = fminf(t2p[mp].y, t.y);
                }
            }
        }
        // per-lane mins -> block t2 table (spread-bank ATOMS, no result dep)
#pragma unroll
        for (int mp = 0; mp < MC / 2; mp++) {
            atomicMin(&s_t2min[(m0 + 2 * mp)     * 32 + lane],
                      __float_as_int(t2p[mp].x));
            atomicMin(&s_t2min[(m0 + 2 * mp + 1) * 32 + lane],
                      __float_as_int(t2p[mp].y));
        }
    }

    // term1 partials: sum p * sqrt(min_m d2), and sum p
    float t1p = 0.0f, pp = 0.0f;
#pragma unroll
    for (int i = 0; i < RR; i++) {
#pragma unroll
        for (int jt = 0; jt < JT; jt++) {
            t1p += pr[i][jt] * sqrtf(pixmin[i][jt]);
            pp  += pr[i][jt];
        }
    }
#pragma unroll
    for (int off = 16; off >= 1; off >>= 1) {
        t1p += __shfl_xor_sync(0xffffffffu, t1p, off);
        pp  += __shfl_xor_sync(0xffffffffu, pp,  off);
    }
    if (lane == 0) { s_red[wrp] = t1p; s_red[4 + wrp] = pp; }
    __syncthreads();   // also covers s_t2min writes
    if (tid == 0) {
        g_t1part[blk] = s_red[0] + s_red[1] + s_red[2] + s_red[3];
        g_ppart[blk]  = s_red[4] + s_red[5] + s_red[6] + s_red[7];
    }

    // block t2 table -> global keys (m = tid, m = 128 + tid if < 192)
    {
        for (int m = tid; m < Mc; m += TPB) {
            const int4* row = (const int4*)&s_t2min[m * 32];
            int4 a = row[0], c = row[1], d = row[2], e = row[3];
            int v0 = min(min(a.x, a.y), min(a.z, a.w));
            int v1 = min(min(c.x, c.y), min(c.z, c.w));
            int v2 = min(min(d.x, d.y), min(d.z, d.w));
            int v3 = min(min(e.x, e.y), min(e.z, e.w));
            int4 f = row[4], g = row[5], h2 = row[6], k2 = row[7];
            int v4 = min(min(f.x, f.y), min(f.z, f.w));
            int v5 = min(min(g.x, g.y), min(g.z, g.w));
            int v6 = min(min(h2.x, h2.y), min(h2.z, h2.w));
            int v7 = min(min(k2.x, k2.y), min(k2.z, k2.w));
            int v = min(min(min(v0, v1), min(v2, v3)),
                        min(min(v4, v5), min(v6, v7)));
            atomicMax(&g_t2key[b * Mc + m], 0x7F800000 - v);
        }
    }

    // ---- last-block finalize ----
    __threadfence();
    __syncthreads();
    if (tid == 0) s_last = (atomicAdd(&g_ctr, 1) == NBLOCKS - 1);
    __syncthreads();
    if (!s_last) return;

    __shared__ float s_t2[Bc], s_t1s[Bc], s_pps[Bc];
    // term2: 768 keys over 128 threads, 6 each; image = tid/32 = wrp
    {
        float acc = 0.0f;
#pragma unroll
        for (int k = 0; k < 6; k++) {
            int idx = tid * 6 + k;
            int key = __ldcg(&g_t2key[idx]);
            float v = __int_as_float(0x7F800000 - key);
            acc += fminf(sqrtf(v), MAXD);
            g_t2key[idx] = 0;                    // reset for next call
        }
#pragma unroll
        for (int off = 16; off >= 1; off >>= 1)
            acc += __shfl_xor_sync(0xffffffffu, acc, off);
        if (lane == 0) s_t2[wrp] = acc;          // warp w == image w
    }
    // term1: warp w reduces the 64 block-partials of image w (2 per lane)
    {
        if (wrp < Bc) {
            float t1 = __ldcg(&g_t1part[wrp * TILES + lane]) +
                       __ldcg(&g_t1part[wrp * TILES + 32 + lane]);
            float ps = __ldcg(&g_ppart [wrp * TILES + lane]) +
                       __ldcg(&g_ppart [wrp * TILES + 32 + lane]);
#pragma unroll
            for (int off = 16; off >= 1; off >>= 1) {
                t1 += __shfl_xor_sync(0xffffffffu, t1, off);
                ps += __shfl_xor_sync(0xffffffffu, ps, off);
            }
            if (lane == 0) { s_t1s[wrp] = t1; s_pps[wrp] = ps; }
        }
    }
    __syncthreads();
    if (tid == 0) {
        float res = 0.0f;
#pragma unroll
        for (int b2 = 0; b2 < Bc; b2++) {
            res += s_t1s[b2] / (s_pps[b2] + EPSc);
            res += s_t2[b2] * (1.0f / (float)Mc);
        }
        out[0] = res * (1.0f / (float)Bc);
        g_ctr = 0;                               // reset for next call
    }
}

extern "C" void kernel_launch(void* const* d_in, const int* in_sizes, int n_in,
                              void* d_out, int out_size) {
    const float* prob = (const float*)d_in[0];
    const float* gt   = (const float*)d_in[1];
    const float* osz  = (const float*)d_in[2];
    float* out = (float*)d_out;

    whd_kernel<<<NBLOCKS, TPB>>>(prob, gt, osz, out);
}